// round 15
// baseline (speedup 1.0000x reference)
#include <cuda_runtime.h>
#include <cuda_fp16.h>
#include <cstdint>

// VoltageNet R14 (= R13 + critical-path & smem-floor micro-opts):
//   out_k = O0 + slD*r_k + I_k*(R0 - U10*C) + R1C*S_k + const   (pointwise)
// Dual prefix sums in ONE scan pass; 2 block barriers; warp-local staging.
// R14: segment LDGs issued first; finalize via 4x STS.128 (smem floor).

#define TT 8192
#define NT 512
#define LL 16
#define REG 1664                     // floats per warp region (32 lanes * 52)
#define FULL 0xFFFFFFFFu
#define SMEM_BYTES (16 * REG * 4)    // 106496 B

__device__ __forceinline__ float tanh_fast(float x) {
    float y; asm("tanh.approx.f32 %0, %1;" : "=f"(y) : "f"(x)); return y;
}
__device__ __forceinline__ float sigmoid_f(float z) {
    return fmaf(tanh_fast(0.5f * z), 0.5f, 0.5f);
}
__device__ __forceinline__ float softplus_f(float x) {
    return fmaxf(x, 0.0f) + __logf(1.0f + __expf(-fabsf(x)));
}
__device__ __forceinline__ int rawslot(int f) { return f + (f / 48) * 4; }
__device__ __forceinline__ int vslot(int g)   { return g + (g >> 5) * 4; }  // 16B-safe

__global__ __launch_bounds__(NT, 2)
void voltage_kernel(const float* __restrict__ X, const float* __restrict__ SC,
                    const float* __restrict__ W1g, const float* __restrict__ b1g,
                    const float* __restrict__ W2g, const float* __restrict__ b2g,
                    float* __restrict__ out)
{
    extern __shared__ float raw[];   // 16 warp regions of REG floats

    __shared__ float sWS[16], sPS[16], sWSe[16], sPSe[16];
    __shared__ float sTr[16], sMnA[16], sMxA[16];
    __shared__ float sW10[6], sW2[30], sB2[5];
    __shared__ float sTmean, sMn, sInvD, sDelta, sI0;

    const int tid  = threadIdx.x;
    const int lane = tid & 31;
    const int wid  = tid >> 5;
    const int b    = blockIdx.x;

    // ---------- phase 0a FIRST: issue the 12 big segment loads immediately ----------
    const float* gbf = X + (size_t)b * (TT * 3) + wid * 1536;
    const float4* gb4 = reinterpret_cast<const float4*>(gbf);
    float4 v0 = gb4[lane];
    float4 v1 = gb4[lane + 32];
    float4 v2 = gb4[lane + 64];
    float4 v3 = gb4[lane + 96];
    float4 v4 = gb4[lane + 128];
    float4 v5 = gb4[lane + 160];
    float4 v6 = gb4[lane + 192];
    float4 v7 = gb4[lane + 224];
    float4 v8 = gb4[lane + 256];
    float4 v9 = gb4[lane + 288];
    float4 va = gb4[lane + 320];
    float4 vb = gb4[lane + 352];

    const float Q  = SC[2 * b + 0];
    const float R0 = SC[2 * b + 1];

    // constant staging overlaps the LDG latency shadow
    if (tid < 6) sW10[tid] = W1g[tid];
    if (tid >= 32 && tid < 62) {
        int i = (tid - 32) / 5, c = (tid - 32) % 5;
        const int col[5] = {0, 1, 2, 5, 6};
        sW2[tid - 32] = W2g[i * 7 + col[c]];
    }
    if (tid >= 64 && tid < 69) {
        const int col[5] = {0, 1, 2, 5, 6};
        sB2[tid - 64] = b2g[col[tid - 64]];
    }

    {
        float* rg = raw + wid * REG;
        float4 vv[12] = {v0,v1,v2,v3,v4,v5,v6,v7,v8,v9,va,vb};
#pragma unroll
        for (int j = 0; j < 12; j++)
            *reinterpret_cast<float4*>(&rg[rawslot(4 * (lane + 32 * j))]) = vv[j];
        if (lane == 0 && wid < 15) {     // boundary (t,I) of next segment into tail
            float2 bd = *reinterpret_cast<const float2*>(gbf + 1536);
            rg[1660] = bd.x; rg[1661] = bd.y;
        }
    }
    __syncwarp();

    // ---------- phase 0b: extract own 16 steps; dual prefixes (soc cum, S cum) ----------
    const float invC = 1.0f / 36000.0f;  // 1/(2*3600*QN), QN=5
    float I[LL + 1];
    __half2 rh[LL / 2], sh[LL / 2];
    float tsum = 0.0f, cum = 0.0f, scum = 0.0f;
    float rmn = 0.0f, rmx = 0.0f, pt = 0.0f;
    float rlo = 0.0f, slo = 0.0f;
    {
        const int sb0 = wid * REG + lane * 52;
#pragma unroll
        for (int s = 0; s < 4; s++) {
            union { float4 q[3]; float f[12]; } u;
            u.q[0] = *reinterpret_cast<float4*>(&raw[sb0 + s * 12]);
            u.q[1] = *reinterpret_cast<float4*>(&raw[sb0 + s * 12 + 4]);
            u.q[2] = *reinterpret_cast<float4*>(&raw[sb0 + s * 12 + 8]);
#pragma unroll
            for (int j = 0; j < 4; j++) {
                int k = s * 4 + j;
                float t  = u.f[3 * j];
                float Ik = u.f[3 * j + 1];
                tsum += u.f[3 * j + 2];
                if (k > 0) {
                    cum  += (Ik + I[k - 1]) * (t - pt) * invC;
                    scum += (Ik - I[k - 1]) * I[k - 1];    // p_{k-1} -> exclusive S
                }
                rmn = fminf(rmn, cum);
                rmx = fmaxf(rmx, cum);
                if ((k & 1) == 0) { rlo = cum; slo = scum; }
                else { rh[k >> 1] = __floats2half2_rn(rlo, cum);
                       sh[k >> 1] = __floats2half2_rn(slo, scum); }
                I[k] = Ik;
                pt = t;
            }
        }
    }
    float dsum, ptot;
    {
        float tb, Ib;
        if (lane < 31) {
            float2 bd = *reinterpret_cast<float2*>(&raw[wid * REG + (lane + 1) * 52]);
            tb = bd.x; Ib = bd.y;
        } else if (wid < 15) {
            float2 bd = *reinterpret_cast<float2*>(&raw[wid * REG + 1660]);
            tb = bd.x; Ib = bd.y;
        } else {                          // tid 511: clamp -> ds=0, p=0
            tb = pt; Ib = I[LL - 1];
        }
        I[LL] = Ib;
        dsum = cum + (Ib + I[LL - 1]) * (tb - pt) * invC;
        ptot = scum + (Ib - I[LL - 1]) * I[LL - 1];
    }
    if (tid == 0) sI0 = I[0];

    // ---------- warp pass: dual inclusive scan (dsum, ptot); reduce tsum/mn/mx ----------
    float v = dsum, pv = ptot;
#pragma unroll
    for (int o = 1; o < 32; o <<= 1) {
        float n  = __shfl_up_sync(FULL, v, o);
        float np = __shfl_up_sync(FULL, pv, o);
        if (lane >= o) { v += n; pv += np; }
    }
    float excl  = __shfl_up_sync(FULL, v, 1);
    float pexcl = __shfl_up_sync(FULL, pv, 1);
    if (lane == 0) { excl = 0.0f; pexcl = 0.0f; }
    {
        float wmn = excl + rmn, wmx = excl + rmx;
#pragma unroll
        for (int o = 16; o > 0; o >>= 1) {
            tsum += __shfl_down_sync(FULL, tsum, o);
            wmn = fminf(wmn, __shfl_down_sync(FULL, wmn, o));
            wmx = fmaxf(wmx, __shfl_down_sync(FULL, wmx, o));
        }
        if (lane == 0) { sTr[wid] = tsum; sMnA[wid] = wmn; sMxA[wid] = wmx; }
    }
    if (lane == 31) { sWS[wid] = v; sPS[wid] = pv; }
    __syncthreads();                                  // barrier #1

    // ---------- block pass (one warp): dual scan of warp totals + Tmean + extremes ----------
    if (tid < 32) {
        float w  = (lane < 16) ? sWS[lane] : 0.0f;
        float pw = (lane < 16) ? sPS[lane] : 0.0f;
#pragma unroll
        for (int o = 1; o < 16; o <<= 1) {
            float n  = __shfl_up_sync(FULL, w, o);
            float np = __shfl_up_sync(FULL, pw, o);
            if (lane >= o) { w += n; pw += np; }
        }
        float e  = __shfl_up_sync(FULL, w, 1);
        float ep = __shfl_up_sync(FULL, pw, 1);
        if (lane == 0) { e = 0.0f; ep = 0.0f; }
        float ts  = (lane < 16) ? sTr[lane] : 0.0f;
        float bmn = (lane < 16) ? e + sMnA[lane] : 3.4e38f;
        float bmx = (lane < 16) ? e + sMxA[lane] : -3.4e38f;
#pragma unroll
        for (int o = 16; o > 0; o >>= 1) {
            ts  += __shfl_down_sync(FULL, ts, o);
            bmn = fminf(bmn, __shfl_down_sync(FULL, bmn, o));
            bmx = fmaxf(bmx, __shfl_down_sync(FULL, bmx, o));
        }
        if (lane < 16) { sWSe[lane] = e; sPSe[lane] = ep; }
        if (lane == 0) {
            sTmean = ts * (1.0f / TT);
            float mn  = fmaf(Q, 0.2f, bmn) - 1e-5f;
            float wdt = (bmx - bmn) + 2e-5f;
            sMn = mn;
            sInvD  = 31.0f / wdt;
            sDelta = wdt * (1.0f / 31.0f);
        }
    }
    __syncthreads();                                  // barrier #2

    // ---------- per-warp register table (OCV, th2); block constants C, R1C ----------
    float tabO, tabT, Cc, Rc;
    {
        float Tm = sTmean;
        float se = fmaf((float)lane, sDelta, sMn);
        float p0 = sB2[0], p1 = sB2[1], p2 = sB2[2], p5 = sB2[3], p6 = sB2[4];
#pragma unroll
        for (int j = 0; j < 6; j++) {
            float c1 = fmaf(R0, W1g[6 + j], fmaf(Tm, W1g[12 + j], b1g[j]));
            float h = softplus_f(fmaf(se, sW10[j], c1));
            p0 = fmaf(h, sW2[j * 5 + 0], p0);
            p1 = fmaf(h, sW2[j * 5 + 1], p1);
            p2 = fmaf(h, sW2[j * 5 + 2], p2);
            p5 = fmaf(h, sW2[j * 5 + 3], p5);
            p6 = fmaf(h, sW2[j * 5 + 4], p6);
        }
        float R1 = 0.04f * sigmoid_f(0.01f * p0);
        float C  = 1e-6f * sigmoid_f(0.01f * p1);
        tabT = fmaf(0.75f, sigmoid_f(0.01f * p2), 0.05f);
        float ox = fmaf(0.79764f, sigmoid_f(0.01f * p5), 0.04236f);
        float oy = fmaf(0.82504f, sigmoid_f(0.01f * p6), 0.023f);

        float up = 4.4167f + oy * (-1.6518f + oy * (1.6225f + oy * (-2.0843f + oy * (3.5146f + oy * (-2.2166f)))));
        up -= 4.0f * __expf(fmaf(109.451f, oy, -100.006f));
        float un = 0.063f + 0.8f * __expf(-75.0f * (ox + 0.001f));
        un -= 0.012f  * tanh_fast(fmaf(ox, 62.5f, -7.9375f));
        un -= 0.0118f * tanh_fast(fmaf(ox, 62.5f, -9.6875f));
        un -= 0.0035f * tanh_fast(fmaf(ox, 50.0f, -11.0f));
        un -= 0.0095f * tanh_fast(fmaf(ox, 76.923076923f, -14.6153846154f));
        un -= 0.0145f * tanh_fast(fmaf(ox, 50.0f, -24.5f));
        un -= 0.08f   * tanh_fast(fmaf(ox, 18.1818181818f, -18.7272727273f));
        tabO = up - un;

        Cc = __shfl_sync(FULL, C, 15);                // mid-range -> block constant
        Rc = __shfl_sync(FULL, R1 * C, 15);
    }

    // ---------- pointwise finalize (per-thread OCV linearization) ----------
    const float mn = sMn, invD = sInvD;
    const float I0 = sI0;
    float U10;
    {   // th2 at soc0 from table (soc0 = Q/QN, inside range)
        int i0 = __float2int_rn((Q * 0.2f - mn) * invD);
        i0 = max(0, min(31, i0));
        float th2 = __shfl_sync(FULL, tabT, i0);
        U10 = -th2 - I0 * R0;
    }
    const float start = fmaf(Q, 0.2f, sWSe[wid] + excl);
    const float Sbase = sPSe[wid] + pexcl;
    const float uc = U10 * Cc;                 // U1 = U10 - uc*(I-I0) + Rc*(Sbase+s)
    const float cI = R0 - uc;                  // coefficient of I_k
    // thread-local OCV line: O(start + r) ~= O0 + slD*r
    float O0, slD;
    {
        float u = (start - mn) * invD;         // in [0, 31]
        int i = (int)u;
        i = max(0, min(30, i));
        float f0 = __shfl_sync(FULL, tabO, i);
        float f1 = __shfl_sync(FULL, tabO, i + 1);
        float df = f1 - f0;
        O0  = fmaf(u - (float)i, df, f0);
        slD = df * invD;
    }
    const float c0 = U10 + uc * I0 + Rc * Sbase + O0;
    float* rg = raw + wid * REG;
#pragma unroll
    for (int m = 0; m < 4; m++) {              // 4 outputs per group -> STS.128
        float2 r01 = __half22float2(rh[2 * m]);
        float2 r23 = __half22float2(rh[2 * m + 1]);
        float2 s01 = __half22float2(sh[2 * m]);
        float2 s23 = __half22float2(sh[2 * m + 1]);
        float4 o;
        o.x = fmaf(r01.x, slD, fmaf(I[4 * m + 0], cI, fmaf(Rc, s01.x, c0)));
        o.y = fmaf(r01.y, slD, fmaf(I[4 * m + 1], cI, fmaf(Rc, s01.y, c0)));
        o.z = fmaf(r23.x, slD, fmaf(I[4 * m + 2], cI, fmaf(Rc, s23.x, c0)));
        o.w = fmaf(r23.y, slD, fmaf(I[4 * m + 3], cI, fmaf(Rc, s23.y, c0)));
        *reinterpret_cast<float4*>(&rg[vslot(lane * LL + 4 * m)]) = o;
    }
    __syncwarp();

    // ---------- warp-local transpose out: LDS.128 + STG.128, fully coalesced ----------
    float* ob = out + (size_t)b * TT + wid * 512;
#pragma unroll
    for (int j = 0; j < 4; j++) {
        int x = 4 * lane + 128 * j;
        float4 w = *reinterpret_cast<float4*>(&rg[vslot(x)]);
        *reinterpret_cast<float4*>(ob + x) = w;
    }
}

extern "C" void kernel_launch(void* const* d_in, const int* in_sizes, int n_in,
                              void* d_out, int out_size)
{
    const float* X  = (const float*)d_in[0];
    const float* SC = (const float*)d_in[1];
    const float* W1 = (const float*)d_in[2];
    const float* b1 = (const float*)d_in[3];
    const float* W2 = (const float*)d_in[4];
    const float* b2 = (const float*)d_in[5];
    int B = in_sizes[1] / 2;   // SC is (B,2)
    cudaFuncSetAttribute(voltage_kernel,
                         cudaFuncAttributeMaxDynamicSharedMemorySize, SMEM_BYTES);
    voltage_kernel<<<B, NT, SMEM_BYTES>>>(X, SC, W1, b1, W2, b2, (float*)d_out);
}

// round 16
// speedup vs baseline: 1.1216x; 1.1216x over previous
#include <cuda_runtime.h>
#include <cuda_fp16.h>
#include <cstdint>

// VoltageNet R15 (= R13 + single-warp shared table):
//   out_k = O0 + slD*r_k + I_k*(R0 - U10*C) + R1C*S_k + const   (pointwise)
// Dual prefix sums in ONE scan pass; 2 block barriers; warp-local staging.
// R15: the 32-entry (OCV, th2) table is computed ONCE by warp 0 inside the
// block-scan section and published in smem — removes 16x duplicated MUFU work.

#define TT 8192
#define NT 512
#define LL 16
#define REG 1664                     // floats per warp region (32 lanes * 52)
#define FULL 0xFFFFFFFFu
#define SMEM_BYTES (16 * REG * 4)    // 106496 B

__device__ __forceinline__ float tanh_fast(float x) {
    float y; asm("tanh.approx.f32 %0, %1;" : "=f"(y) : "f"(x)); return y;
}
__device__ __forceinline__ float sigmoid_f(float z) {
    return fmaf(tanh_fast(0.5f * z), 0.5f, 0.5f);
}
__device__ __forceinline__ float softplus_f(float x) {
    return fmaxf(x, 0.0f) + __logf(1.0f + __expf(-fabsf(x)));
}
__device__ __forceinline__ int rawslot(int f) { return f + (f / 48) * 4; }
__device__ __forceinline__ int vslot(int g)   { return g + (g >> 5) * 4; }  // 16B-safe

__global__ __launch_bounds__(NT, 2)
void voltage_kernel(const float* __restrict__ X, const float* __restrict__ SC,
                    const float* __restrict__ W1g, const float* __restrict__ b1g,
                    const float* __restrict__ W2g, const float* __restrict__ b2g,
                    float* __restrict__ out)
{
    extern __shared__ float raw[];   // 16 warp regions of REG floats

    __shared__ float sWS[16], sPS[16], sWSe[16], sPSe[16];
    __shared__ float sTr[16], sMnA[16], sMxA[16];
    __shared__ float sW10[6], sW2[30], sB2[5];
    __shared__ float sTabO[32], sTabT[32];
    __shared__ float sMn, sInvD, sI0, sCc, sRc;

    const int tid  = threadIdx.x;
    const int lane = tid & 31;
    const int wid  = tid >> 5;
    const int b    = blockIdx.x;

    const float Q  = SC[2 * b + 0];
    const float R0 = SC[2 * b + 1];

    // stage MLP constants (W1 soc-col; W2 cols {0,1,2,5,6}; matching b2)
    if (tid < 6) sW10[tid] = W1g[tid];
    if (tid >= 32 && tid < 62) {
        int i = (tid - 32) / 5, c = (tid - 32) % 5;
        const int col[5] = {0, 1, 2, 5, 6};
        sW2[tid - 32] = W2g[i * 7 + col[c]];
    }
    if (tid >= 64 && tid < 69) {
        const int col[5] = {0, 1, 2, 5, 6};
        sB2[tid - 64] = b2g[col[tid - 64]];
    }

    // ---------- phase 0a: warp-local coalesced load of own 512-step segment ----------
    const float* gbf = X + (size_t)b * (TT * 3) + wid * 1536;
    {
        const float4* gb4 = reinterpret_cast<const float4*>(gbf);
        float* rg = raw + wid * REG;
#pragma unroll
        for (int j = 0; j < 12; j++) {
            float4 v = gb4[lane + 32 * j];
            *reinterpret_cast<float4*>(&rg[rawslot(4 * (lane + 32 * j))]) = v;
        }
        if (lane == 0 && wid < 15) {     // boundary (t,I) of next segment into tail
            float2 bd = *reinterpret_cast<const float2*>(gbf + 1536);
            rg[1660] = bd.x; rg[1661] = bd.y;
        }
    }
    __syncwarp();

    // ---------- phase 0b: extract own 16 steps; dual prefixes (soc cum, S cum) ----------
    const float invC = 1.0f / 36000.0f;  // 1/(2*3600*QN), QN=5
    float I[LL + 1];
    __half2 rh[LL / 2], sh[LL / 2];
    float tsum = 0.0f, cum = 0.0f, scum = 0.0f;
    float rmn = 0.0f, rmx = 0.0f, pt = 0.0f;
    float rlo = 0.0f, slo = 0.0f;
    {
        const int sb0 = wid * REG + lane * 52;
#pragma unroll
        for (int s = 0; s < 4; s++) {
            union { float4 q[3]; float f[12]; } u;
            u.q[0] = *reinterpret_cast<float4*>(&raw[sb0 + s * 12]);
            u.q[1] = *reinterpret_cast<float4*>(&raw[sb0 + s * 12 + 4]);
            u.q[2] = *reinterpret_cast<float4*>(&raw[sb0 + s * 12 + 8]);
#pragma unroll
            for (int j = 0; j < 4; j++) {
                int k = s * 4 + j;
                float t  = u.f[3 * j];
                float Ik = u.f[3 * j + 1];
                tsum += u.f[3 * j + 2];
                if (k > 0) {
                    cum  += (Ik + I[k - 1]) * (t - pt) * invC;
                    scum += (Ik - I[k - 1]) * I[k - 1];    // p_{k-1} -> exclusive S
                }
                rmn = fminf(rmn, cum);
                rmx = fmaxf(rmx, cum);
                if ((k & 1) == 0) { rlo = cum; slo = scum; }
                else { rh[k >> 1] = __floats2half2_rn(rlo, cum);
                       sh[k >> 1] = __floats2half2_rn(slo, scum); }
                I[k] = Ik;
                pt = t;
            }
        }
    }
    float dsum, ptot;
    {
        float tb, Ib;
        if (lane < 31) {
            float2 bd = *reinterpret_cast<float2*>(&raw[wid * REG + (lane + 1) * 52]);
            tb = bd.x; Ib = bd.y;
        } else if (wid < 15) {
            float2 bd = *reinterpret_cast<float2*>(&raw[wid * REG + 1660]);
            tb = bd.x; Ib = bd.y;
        } else {                          // tid 511: clamp -> ds=0, p=0
            tb = pt; Ib = I[LL - 1];
        }
        I[LL] = Ib;
        dsum = cum + (Ib + I[LL - 1]) * (tb - pt) * invC;
        ptot = scum + (Ib - I[LL - 1]) * I[LL - 1];
    }
    if (tid == 0) sI0 = I[0];

    // ---------- warp pass: dual inclusive scan (dsum, ptot); reduce tsum/mn/mx ----------
    float v = dsum, pv = ptot;
#pragma unroll
    for (int o = 1; o < 32; o <<= 1) {
        float n  = __shfl_up_sync(FULL, v, o);
        float np = __shfl_up_sync(FULL, pv, o);
        if (lane >= o) { v += n; pv += np; }
    }
    float excl  = __shfl_up_sync(FULL, v, 1);
    float pexcl = __shfl_up_sync(FULL, pv, 1);
    if (lane == 0) { excl = 0.0f; pexcl = 0.0f; }
    {
        float wmn = excl + rmn, wmx = excl + rmx;
#pragma unroll
        for (int o = 16; o > 0; o >>= 1) {
            tsum += __shfl_down_sync(FULL, tsum, o);
            wmn = fminf(wmn, __shfl_down_sync(FULL, wmn, o));
            wmx = fmaxf(wmx, __shfl_down_sync(FULL, wmx, o));
        }
        if (lane == 0) { sTr[wid] = tsum; sMnA[wid] = wmn; sMxA[wid] = wmx; }
    }
    if (lane == 31) { sWS[wid] = v; sPS[wid] = pv; }
    __syncthreads();                                  // barrier #1

    // ---------- block pass (warp 0): dual scan + Tmean + extremes + SHARED TABLE ----------
    if (tid < 32) {
        float w  = (lane < 16) ? sWS[lane] : 0.0f;
        float pw = (lane < 16) ? sPS[lane] : 0.0f;
#pragma unroll
        for (int o = 1; o < 16; o <<= 1) {
            float n  = __shfl_up_sync(FULL, w, o);
            float np = __shfl_up_sync(FULL, pw, o);
            if (lane >= o) { w += n; pw += np; }
        }
        float e  = __shfl_up_sync(FULL, w, 1);
        float ep = __shfl_up_sync(FULL, pw, 1);
        if (lane == 0) { e = 0.0f; ep = 0.0f; }
        float ts  = (lane < 16) ? sTr[lane] : 0.0f;
        float bmn = (lane < 16) ? e + sMnA[lane] : 3.4e38f;
        float bmx = (lane < 16) ? e + sMxA[lane] : -3.4e38f;
#pragma unroll
        for (int o = 16; o > 0; o >>= 1) {
            ts  += __shfl_down_sync(FULL, ts, o);
            bmn = fminf(bmn, __shfl_down_sync(FULL, bmn, o));
            bmx = fmaxf(bmx, __shfl_down_sync(FULL, bmx, o));
        }
        if (lane < 16) { sWSe[lane] = e; sPSe[lane] = ep; }

        // broadcast full reductions to all 32 lanes of warp 0
        float Tm  = __shfl_sync(FULL, ts, 0) * (1.0f / TT);
        float bmnF = __shfl_sync(FULL, bmn, 0);
        float bmxF = __shfl_sync(FULL, bmx, 0);
        float mn  = fmaf(Q, 0.2f, bmnF) - 1e-5f;
        float wdt = (bmxF - bmnF) + 2e-5f;
        float invD  = 31.0f / wdt;
        float delta = wdt * (1.0f / 31.0f);
        if (lane == 0) { sMn = mn; sInvD = invD; }

        // lane l computes table entry l (the ONLY transcendental block in the CTA)
        float se = fmaf((float)lane, delta, mn);
        float p0 = sB2[0], p1 = sB2[1], p2 = sB2[2], p5 = sB2[3], p6 = sB2[4];
#pragma unroll
        for (int j = 0; j < 6; j++) {
            float c1 = fmaf(R0, W1g[6 + j], fmaf(Tm, W1g[12 + j], b1g[j]));
            float h = softplus_f(fmaf(se, sW10[j], c1));
            p0 = fmaf(h, sW2[j * 5 + 0], p0);
            p1 = fmaf(h, sW2[j * 5 + 1], p1);
            p2 = fmaf(h, sW2[j * 5 + 2], p2);
            p5 = fmaf(h, sW2[j * 5 + 3], p5);
            p6 = fmaf(h, sW2[j * 5 + 4], p6);
        }
        float R1 = 0.04f * sigmoid_f(0.01f * p0);
        float C  = 1e-6f * sigmoid_f(0.01f * p1);
        sTabT[lane] = fmaf(0.75f, sigmoid_f(0.01f * p2), 0.05f);
        float ox = fmaf(0.79764f, sigmoid_f(0.01f * p5), 0.04236f);
        float oy = fmaf(0.82504f, sigmoid_f(0.01f * p6), 0.023f);

        float up = 4.4167f + oy * (-1.6518f + oy * (1.6225f + oy * (-2.0843f + oy * (3.5146f + oy * (-2.2166f)))));
        up -= 4.0f * __expf(fmaf(109.451f, oy, -100.006f));
        float un = 0.063f + 0.8f * __expf(-75.0f * (ox + 0.001f));
        un -= 0.012f  * tanh_fast(fmaf(ox, 62.5f, -7.9375f));
        un -= 0.0118f * tanh_fast(fmaf(ox, 62.5f, -9.6875f));
        un -= 0.0035f * tanh_fast(fmaf(ox, 50.0f, -11.0f));
        un -= 0.0095f * tanh_fast(fmaf(ox, 76.923076923f, -14.6153846154f));
        un -= 0.0145f * tanh_fast(fmaf(ox, 50.0f, -24.5f));
        un -= 0.08f   * tanh_fast(fmaf(ox, 18.1818181818f, -18.7272727273f));
        sTabO[lane] = up - un;
        if (lane == 15) { sCc = C; sRc = R1 * C; }    // mid-range block constants
    }
    __syncthreads();                                  // barrier #2 (table published)

    // ---------- pointwise finalize (per-thread OCV linearization from smem table) ----------
    const float mn = sMn, invD = sInvD;
    const float Cc = sCc, Rc = sRc;
    const float I0 = sI0;
    float U10;
    {   // th2 at soc0 (same index for all threads -> broadcast LDS)
        int i0 = __float2int_rn((Q * 0.2f - mn) * invD);
        i0 = max(0, min(31, i0));
        U10 = -sTabT[i0] - I0 * R0;
    }
    const float start = fmaf(Q, 0.2f, sWSe[wid] + excl);
    const float Sbase = sPSe[wid] + pexcl;
    const float uc = U10 * Cc;                 // U1 = U10 - uc*(I-I0) + Rc*(Sbase+s)
    const float cI = R0 - uc;                  // coefficient of I_k
    // thread-local OCV line: O(start + r) ~= O0 + slD*r
    float O0, slD;
    {
        float u = (start - mn) * invD;         // in [0, 31]
        int i = (int)u;
        i = max(0, min(30, i));
        float f0 = sTabO[i];
        float f1 = sTabO[i + 1];
        float df = f1 - f0;
        O0  = fmaf(u - (float)i, df, f0);
        slD = df * invD;
    }
    const float c0 = U10 + uc * I0 + Rc * Sbase + O0;
    float* rg = raw + wid * REG;
#pragma unroll
    for (int k = 0; k < LL; k++) {
        float2 rr = __half22float2(rh[k >> 1]);
        float rk = (k & 1) ? rr.y : rr.x;
        float2 ss = __half22float2(sh[k >> 1]);
        float sk = (k & 1) ? ss.y : ss.x;
        rg[vslot(lane * LL + k)] =
            fmaf(rk, slD, fmaf(I[k], cI, fmaf(Rc, sk, c0)));
    }
    __syncwarp();

    // ---------- warp-local transpose out: LDS.128 + STG.128, fully coalesced ----------
    float* ob = out + (size_t)b * TT + wid * 512;
#pragma unroll
    for (int j = 0; j < 4; j++) {
        int x = 4 * lane + 128 * j;
        float4 w = *reinterpret_cast<float4*>(&rg[vslot(x)]);
        *reinterpret_cast<float4*>(ob + x) = w;
    }
}

extern "C" void kernel_launch(void* const* d_in, const int* in_sizes, int n_in,
                              void* d_out, int out_size)
{
    const float* X  = (const float*)d_in[0];
    const float* SC = (const float*)d_in[1];
    const float* W1 = (const float*)d_in[2];
    const float* b1 = (const float*)d_in[3];
    const float* W2 = (const float*)d_in[4];
    const float* b2 = (const float*)d_in[5];
    int B = in_sizes[1] / 2;   // SC is (B,2)
    cudaFuncSetAttribute(voltage_kernel,
                         cudaFuncAttributeMaxDynamicSharedMemorySize, SMEM_BYTES);
    voltage_kernel<<<B, NT, SMEM_BYTES>>>(X, SC, W1, b1, W2, b2, (float*)d_out);
}

// round 17
// speedup vs baseline: 1.1235x; 1.0017x over previous
#include <cuda_runtime.h>
#include <cuda_fp16.h>
#include <cstdint>

// VoltageNet R16 (= R15 + STS.128 finalize + exact-U10-from-warp0):
//   out_k = O0 + slD*r_k + I_k*(R0 - U10*C) + R1C*S_k + const   (pointwise)
// Dual prefix sums in ONE scan pass; 2 block barriers; warp-local staging.
// Table: 31 entries (lanes 0..30); lane 31 evaluates th2 at soc0 exactly -> sU10.

#define TT 8192
#define NT 512
#define LL 16
#define REG 1664                     // floats per warp region (32 lanes * 52)
#define FULL 0xFFFFFFFFu
#define SMEM_BYTES (16 * REG * 4)    // 106496 B

__device__ __forceinline__ float tanh_fast(float x) {
    float y; asm("tanh.approx.f32 %0, %1;" : "=f"(y) : "f"(x)); return y;
}
__device__ __forceinline__ float sigmoid_f(float z) {
    return fmaf(tanh_fast(0.5f * z), 0.5f, 0.5f);
}
__device__ __forceinline__ float softplus_f(float x) {
    return fmaxf(x, 0.0f) + __logf(1.0f + __expf(-fabsf(x)));
}
__device__ __forceinline__ int rawslot(int f) { return f + (f / 48) * 4; }
__device__ __forceinline__ int vslot(int g)   { return g + (g >> 5) * 4; }  // 16B-safe

__global__ __launch_bounds__(NT, 2)
void voltage_kernel(const float* __restrict__ X, const float* __restrict__ SC,
                    const float* __restrict__ W1g, const float* __restrict__ b1g,
                    const float* __restrict__ W2g, const float* __restrict__ b2g,
                    float* __restrict__ out)
{
    extern __shared__ float raw[];   // 16 warp regions of REG floats

    __shared__ float sWS[16], sPS[16], sWSe[16], sPSe[16];
    __shared__ float sTr[16], sMnA[16], sMxA[16];
    __shared__ float sW10[6], sW2[30], sB2[5];
    __shared__ float sTabO[32];
    __shared__ float sMn, sInvD, sI0, sCc, sRc, sU10;

    const int tid  = threadIdx.x;
    const int lane = tid & 31;
    const int wid  = tid >> 5;
    const int b    = blockIdx.x;

    const float Q  = SC[2 * b + 0];
    const float R0 = SC[2 * b + 1];

    // stage MLP constants (W1 soc-col; W2 cols {0,1,2,5,6}; matching b2)
    if (tid < 6) sW10[tid] = W1g[tid];
    if (tid >= 32 && tid < 62) {
        int i = (tid - 32) / 5, c = (tid - 32) % 5;
        const int col[5] = {0, 1, 2, 5, 6};
        sW2[tid - 32] = W2g[i * 7 + col[c]];
    }
    if (tid >= 64 && tid < 69) {
        const int col[5] = {0, 1, 2, 5, 6};
        sB2[tid - 64] = b2g[col[tid - 64]];
    }

    // ---------- phase 0a: warp-local coalesced load of own 512-step segment ----------
    const float* gbf = X + (size_t)b * (TT * 3) + wid * 1536;
    {
        const float4* gb4 = reinterpret_cast<const float4*>(gbf);
        float* rg = raw + wid * REG;
#pragma unroll
        for (int j = 0; j < 12; j++) {
            float4 v = gb4[lane + 32 * j];
            *reinterpret_cast<float4*>(&rg[rawslot(4 * (lane + 32 * j))]) = v;
        }
        if (lane == 0 && wid < 15) {     // boundary (t,I) of next segment into tail
            float2 bd = *reinterpret_cast<const float2*>(gbf + 1536);
            rg[1660] = bd.x; rg[1661] = bd.y;
        }
    }
    __syncwarp();

    // ---------- phase 0b: extract own 16 steps; dual prefixes (soc cum, S cum) ----------
    const float invC = 1.0f / 36000.0f;  // 1/(2*3600*QN), QN=5
    float I[LL + 1];
    __half2 rh[LL / 2], sh[LL / 2];
    float tsum = 0.0f, cum = 0.0f, scum = 0.0f;
    float rmn = 0.0f, rmx = 0.0f, pt = 0.0f;
    float rlo = 0.0f, slo = 0.0f;
    {
        const int sb0 = wid * REG + lane * 52;
#pragma unroll
        for (int s = 0; s < 4; s++) {
            union { float4 q[3]; float f[12]; } u;
            u.q[0] = *reinterpret_cast<float4*>(&raw[sb0 + s * 12]);
            u.q[1] = *reinterpret_cast<float4*>(&raw[sb0 + s * 12 + 4]);
            u.q[2] = *reinterpret_cast<float4*>(&raw[sb0 + s * 12 + 8]);
#pragma unroll
            for (int j = 0; j < 4; j++) {
                int k = s * 4 + j;
                float t  = u.f[3 * j];
                float Ik = u.f[3 * j + 1];
                tsum += u.f[3 * j + 2];
                if (k > 0) {
                    cum  += (Ik + I[k - 1]) * (t - pt) * invC;
                    scum += (Ik - I[k - 1]) * I[k - 1];    // p_{k-1} -> exclusive S
                }
                rmn = fminf(rmn, cum);
                rmx = fmaxf(rmx, cum);
                if ((k & 1) == 0) { rlo = cum; slo = scum; }
                else { rh[k >> 1] = __floats2half2_rn(rlo, cum);
                       sh[k >> 1] = __floats2half2_rn(slo, scum); }
                I[k] = Ik;
                pt = t;
            }
        }
    }
    float dsum, ptot;
    {
        float tb, Ib;
        if (lane < 31) {
            float2 bd = *reinterpret_cast<float2*>(&raw[wid * REG + (lane + 1) * 52]);
            tb = bd.x; Ib = bd.y;
        } else if (wid < 15) {
            float2 bd = *reinterpret_cast<float2*>(&raw[wid * REG + 1660]);
            tb = bd.x; Ib = bd.y;
        } else {                          // tid 511: clamp -> ds=0, p=0
            tb = pt; Ib = I[LL - 1];
        }
        I[LL] = Ib;
        dsum = cum + (Ib + I[LL - 1]) * (tb - pt) * invC;
        ptot = scum + (Ib - I[LL - 1]) * I[LL - 1];
    }
    if (tid == 0) sI0 = I[0];

    // ---------- warp pass: dual inclusive scan (dsum, ptot); reduce tsum/mn/mx ----------
    float v = dsum, pv = ptot;
#pragma unroll
    for (int o = 1; o < 32; o <<= 1) {
        float n  = __shfl_up_sync(FULL, v, o);
        float np = __shfl_up_sync(FULL, pv, o);
        if (lane >= o) { v += n; pv += np; }
    }
    float excl  = __shfl_up_sync(FULL, v, 1);
    float pexcl = __shfl_up_sync(FULL, pv, 1);
    if (lane == 0) { excl = 0.0f; pexcl = 0.0f; }
    {
        float wmn = excl + rmn, wmx = excl + rmx;
#pragma unroll
        for (int o = 16; o > 0; o >>= 1) {
            tsum += __shfl_down_sync(FULL, tsum, o);
            wmn = fminf(wmn, __shfl_down_sync(FULL, wmn, o));
            wmx = fmaxf(wmx, __shfl_down_sync(FULL, wmx, o));
        }
        if (lane == 0) { sTr[wid] = tsum; sMnA[wid] = wmn; sMxA[wid] = wmx; }
    }
    if (lane == 31) { sWS[wid] = v; sPS[wid] = pv; }
    __syncthreads();                                  // barrier #1

    // ---------- block pass (warp 0): dual scan + Tmean + extremes + SHARED TABLE ----------
    if (tid < 32) {
        float w  = (lane < 16) ? sWS[lane] : 0.0f;
        float pw = (lane < 16) ? sPS[lane] : 0.0f;
#pragma unroll
        for (int o = 1; o < 16; o <<= 1) {
            float n  = __shfl_up_sync(FULL, w, o);
            float np = __shfl_up_sync(FULL, pw, o);
            if (lane >= o) { w += n; pw += np; }
        }
        float e  = __shfl_up_sync(FULL, w, 1);
        float ep = __shfl_up_sync(FULL, pw, 1);
        if (lane == 0) { e = 0.0f; ep = 0.0f; }
        float ts  = (lane < 16) ? sTr[lane] : 0.0f;
        float bmn = (lane < 16) ? e + sMnA[lane] : 3.4e38f;
        float bmx = (lane < 16) ? e + sMxA[lane] : -3.4e38f;
#pragma unroll
        for (int o = 16; o > 0; o >>= 1) {
            ts  += __shfl_down_sync(FULL, ts, o);
            bmn = fminf(bmn, __shfl_down_sync(FULL, bmn, o));
            bmx = fmaxf(bmx, __shfl_down_sync(FULL, bmx, o));
        }
        if (lane < 16) { sWSe[lane] = e; sPSe[lane] = ep; }

        // broadcast full reductions to all 32 lanes of warp 0
        float Tm  = __shfl_sync(FULL, ts, 0) * (1.0f / TT);
        float bmnF = __shfl_sync(FULL, bmn, 0);
        float bmxF = __shfl_sync(FULL, bmx, 0);
        float mn  = fmaf(Q, 0.2f, bmnF) - 1e-5f;
        float wdt = (bmxF - bmnF) + 2e-5f;
        float invD  = 30.0f / wdt;                    // 31-entry table (lanes 0..30)
        float delta = wdt * (1.0f / 30.0f);
        if (lane == 0) { sMn = mn; sInvD = invD; }

        // lanes 0..30: table entry; lane 31: exact eval at soc0 (for U10)
        float se = (lane == 31) ? (Q * 0.2f) : fmaf((float)lane, delta, mn);
        float p0 = sB2[0], p1 = sB2[1], p2 = sB2[2], p5 = sB2[3], p6 = sB2[4];
#pragma unroll
        for (int j = 0; j < 6; j++) {
            float c1 = fmaf(R0, W1g[6 + j], fmaf(Tm, W1g[12 + j], b1g[j]));
            float h = softplus_f(fmaf(se, sW10[j], c1));
            p0 = fmaf(h, sW2[j * 5 + 0], p0);
            p1 = fmaf(h, sW2[j * 5 + 1], p1);
            p2 = fmaf(h, sW2[j * 5 + 2], p2);
            p5 = fmaf(h, sW2[j * 5 + 3], p5);
            p6 = fmaf(h, sW2[j * 5 + 4], p6);
        }
        float R1 = 0.04f * sigmoid_f(0.01f * p0);
        float C  = 1e-6f * sigmoid_f(0.01f * p1);
        float th2 = fmaf(0.75f, sigmoid_f(0.01f * p2), 0.05f);
        float ox = fmaf(0.79764f, sigmoid_f(0.01f * p5), 0.04236f);
        float oy = fmaf(0.82504f, sigmoid_f(0.01f * p6), 0.023f);

        float up = 4.4167f + oy * (-1.6518f + oy * (1.6225f + oy * (-2.0843f + oy * (3.5146f + oy * (-2.2166f)))));
        up -= 4.0f * __expf(fmaf(109.451f, oy, -100.006f));
        float un = 0.063f + 0.8f * __expf(-75.0f * (ox + 0.001f));
        un -= 0.012f  * tanh_fast(fmaf(ox, 62.5f, -7.9375f));
        un -= 0.0118f * tanh_fast(fmaf(ox, 62.5f, -9.6875f));
        un -= 0.0035f * tanh_fast(fmaf(ox, 50.0f, -11.0f));
        un -= 0.0095f * tanh_fast(fmaf(ox, 76.923076923f, -14.6153846154f));
        un -= 0.0145f * tanh_fast(fmaf(ox, 50.0f, -24.5f));
        un -= 0.08f   * tanh_fast(fmaf(ox, 18.1818181818f, -18.7272727273f));
        if (lane < 31) sTabO[lane] = up - un;
        if (lane == 31) sU10 = -th2 - sI0 * R0;       // exact U1(0)
        if (lane == 15) { sCc = C; sRc = R1 * C; }    // mid-range block constants
    }
    __syncthreads();                                  // barrier #2 (table published)

    // ---------- pointwise finalize (per-thread OCV linearization from smem table) ----------
    const float mn = sMn, invD = sInvD;
    const float Cc = sCc, Rc = sRc;
    const float I0 = sI0;
    const float U10 = sU10;
    const float start = fmaf(Q, 0.2f, sWSe[wid] + excl);
    const float Sbase = sPSe[wid] + pexcl;
    const float uc = U10 * Cc;                 // U1 = U10 - uc*(I-I0) + Rc*(Sbase+s)
    const float cI = R0 - uc;                  // coefficient of I_k
    // thread-local OCV line: O(start + r) ~= O0 + slD*r
    float O0, slD;
    {
        float u = (start - mn) * invD;         // in [0, 30]
        int i = (int)u;
        i = max(0, min(29, i));
        float f0 = sTabO[i];
        float f1 = sTabO[i + 1];
        float df = f1 - f0;
        O0  = fmaf(u - (float)i, df, f0);
        slD = df * invD;
    }
    const float c0 = U10 + uc * I0 + Rc * Sbase + O0;
    float* rg = raw + wid * REG;
#pragma unroll
    for (int m = 0; m < 4; m++) {              // 4 outputs per group -> STS.128
        float2 r01 = __half22float2(rh[2 * m]);
        float2 r23 = __half22float2(rh[2 * m + 1]);
        float2 s01 = __half22float2(sh[2 * m]);
        float2 s23 = __half22float2(sh[2 * m + 1]);
        float4 o;
        o.x = fmaf(r01.x, slD, fmaf(I[4 * m + 0], cI, fmaf(Rc, s01.x, c0)));
        o.y = fmaf(r01.y, slD, fmaf(I[4 * m + 1], cI, fmaf(Rc, s01.y, c0)));
        o.z = fmaf(r23.x, slD, fmaf(I[4 * m + 2], cI, fmaf(Rc, s23.x, c0)));
        o.w = fmaf(r23.y, slD, fmaf(I[4 * m + 3], cI, fmaf(Rc, s23.y, c0)));
        *reinterpret_cast<float4*>(&rg[vslot(lane * LL + 4 * m)]) = o;
    }
    __syncwarp();

    // ---------- warp-local transpose out: LDS.128 + STG.128, fully coalesced ----------
    float* ob = out + (size_t)b * TT + wid * 512;
#pragma unroll
    for (int j = 0; j < 4; j++) {
        int x = 4 * lane + 128 * j;
        float4 w = *reinterpret_cast<float4*>(&rg[vslot(x)]);
        *reinterpret_cast<float4*>(ob + x) = w;
    }
}

extern "C" void kernel_launch(void* const* d_in, const int* in_sizes, int n_in,
                              void* d_out, int out_size)
{
    const float* X  = (const float*)d_in[0];
    const float* SC = (const float*)d_in[1];
    const float* W1 = (const float*)d_in[2];
    const float* b1 = (const float*)d_in[3];
    const float* W2 = (const float*)d_in[4];
    const float* b2 = (const float*)d_in[5];
    int B = in_sizes[1] / 2;   // SC is (B,2)
    cudaFuncSetAttribute(voltage_kernel,
                         cudaFuncAttributeMaxDynamicSharedMemorySize, SMEM_BYTES);
    voltage_kernel<<<B, NT, SMEM_BYTES>>>(X, SC, W1, b1, W2, b2, (float*)d_out);
}